// round 1
// baseline (speedup 1.0000x reference)
#include <cuda_runtime.h>

// GEMV: out[i] = dot(inputs[i, 0:272], weights[0:272]) + bias
// weights[0:16]   = kernel
// weights[16+p]   = kernel[i0]*kernel[i3]*w1 + kernel[i1]*kernel[i2]*w2
//   where p = x1*16 + x2; a1=x1/4, b1=x1%4, a2=x2/4, b2=x2%4;
//   i0=4a1+a2, i1=4a1+b2, i2=4b1+a2, i3=4b1+b2.

#define D 272
#define NV4 (D / 4)   // 68

__global__ __launch_bounds__(256) void gemv272_kernel(
    const float* __restrict__ inputs,
    const float* __restrict__ kern,
    const float* __restrict__ w1,
    const float* __restrict__ w2,
    const float* __restrict__ bias,
    float* __restrict__ out,
    int n)
{
    __shared__ float w[D];
    __shared__ float sbias;

    const int t = threadIdx.x;

    // Build the 272-element weight vector cooperatively (cheap, per block).
    if (t < 16) {
        w[t] = kern[t];
    }
    {
        // threads 0..255 each compute one pairwise weight
        const int x1 = t >> 4;
        const int x2 = t & 15;
        const int a1 = x1 >> 2, b1 = x1 & 3;
        const int a2 = x2 >> 2, b2 = x2 & 3;
        const float k0 = kern[4 * a1 + a2];
        const float k1 = kern[4 * a1 + b2];
        const float k2 = kern[4 * b1 + a2];
        const float k3 = kern[4 * b1 + b2];
        w[16 + t] = k0 * k3 * w1[0] + k1 * k2 * w2[0];
    }
    if (t == 0) sbias = bias[0];
    __syncthreads();

    const int i = blockIdx.x * 256 + t;
    if (i >= n) return;

    // Row is 272 floats = 1088 bytes, 16B-aligned for every i.
    const float4* __restrict__ row =
        reinterpret_cast<const float4*>(inputs + (size_t)i * D);
    const float4* __restrict__ wv = reinterpret_cast<const float4*>(w);

    float acc0 = 0.f, acc1 = 0.f, acc2 = 0.f, acc3 = 0.f;

#pragma unroll
    for (int j = 0; j < NV4; j++) {
        const float4 v = row[j];
        const float4 ww = wv[j];
        acc0 = fmaf(v.x, ww.x, acc0);
        acc1 = fmaf(v.y, ww.y, acc1);
        acc2 = fmaf(v.z, ww.z, acc2);
        acc3 = fmaf(v.w, ww.w, acc3);
    }

    out[i] = (acc0 + acc1) + (acc2 + acc3) + sbias;
}

extern "C" void kernel_launch(void* const* d_in, const int* in_sizes, int n_in,
                              void* d_out, int out_size)
{
    const float* inputs = (const float*)d_in[0];
    const float* kern   = (const float*)d_in[1];
    const float* w1     = (const float*)d_in[2];
    const float* w2     = (const float*)d_in[3];
    const float* bias   = (const float*)d_in[4];
    float* out = (float*)d_out;

    const int n = out_size;  // 500000 rows
    const int threads = 256;
    const int blocks = (n + threads - 1) / threads;
    gemv272_kernel<<<blocks, threads>>>(inputs, kern, w1, w2, bias, out, n);
}

// round 2
// speedup vs baseline: 1.2163x; 1.2163x over previous
#include <cuda_runtime.h>

// GEMV: out[i] = dot(inputs[i, 0:272], weights[0:272]) + bias
// Warp-per-row, lane-per-column (coalesced 512B spans), shfl reduce.

#define D 272
#define NV4 (D / 4)          // 68 float4 per row
#define WARPS_PER_BLOCK 8
#define THREADS (WARPS_PER_BLOCK * 32)

__global__ __launch_bounds__(THREADS) void gemv272_warp_kernel(
    const float* __restrict__ inputs,
    const float* __restrict__ kern,
    const float* __restrict__ w1,
    const float* __restrict__ w2,
    const float* __restrict__ bias,
    float* __restrict__ out,
    int n)
{
    __shared__ float w[D];     // 272 weights, 16B aligned
    __shared__ float sbias;

    const int t = threadIdx.x;

    // Build weight vector: 16 linear + 256 pairwise (one per thread).
    if (t < 16) w[t] = kern[t];
    {
        const int x1 = t >> 4, x2 = t & 15;
        const int a1 = x1 >> 2, b1 = x1 & 3;
        const int a2 = x2 >> 2, b2 = x2 & 3;
        const float k0 = kern[4 * a1 + a2];
        const float k1 = kern[4 * a1 + b2];
        const float k2 = kern[4 * b1 + a2];
        const float k3 = kern[4 * b1 + b2];
        w[16 + t] = k0 * k3 * w1[0] + k1 * k2 * w2[0];
    }
    if (t == 0) sbias = bias[0];
    __syncthreads();

    const int warp = t >> 5;
    const int lane = t & 31;
    const int row  = blockIdx.x * WARPS_PER_BLOCK + warp;
    if (row >= n) return;

    const float4* __restrict__ rp =
        reinterpret_cast<const float4*>(inputs) + (size_t)row * NV4;
    const float4* __restrict__ wv = reinterpret_cast<const float4*>(w);

    // Issue all loads up front (MLP=3 per warp).
    const float4 v0 = rp[lane];
    const float4 v1 = rp[32 + lane];
    float4 v2 = make_float4(0.f, 0.f, 0.f, 0.f);
    if (lane < 4) v2 = rp[64 + lane];

    const float4 w0 = wv[lane];
    const float4 w1v = wv[32 + lane];
    float4 w2v = make_float4(0.f, 0.f, 0.f, 0.f);
    if (lane < 4) w2v = wv[64 + lane];

    float acc = v0.x * w0.x;
    acc = fmaf(v0.y, w0.y, acc);
    acc = fmaf(v0.z, w0.z, acc);
    acc = fmaf(v0.w, w0.w, acc);
    acc = fmaf(v1.x, w1v.x, acc);
    acc = fmaf(v1.y, w1v.y, acc);
    acc = fmaf(v1.z, w1v.z, acc);
    acc = fmaf(v1.w, w1v.w, acc);
    acc = fmaf(v2.x, w2v.x, acc);
    acc = fmaf(v2.y, w2v.y, acc);
    acc = fmaf(v2.z, w2v.z, acc);
    acc = fmaf(v2.w, w2v.w, acc);

    // Warp reduction.
#pragma unroll
    for (int off = 16; off > 0; off >>= 1)
        acc += __shfl_xor_sync(0xFFFFFFFFu, acc, off);

    if (lane == 0) out[row] = acc + sbias;
}

extern "C" void kernel_launch(void* const* d_in, const int* in_sizes, int n_in,
                              void* d_out, int out_size)
{
    const float* inputs = (const float*)d_in[0];
    const float* kern   = (const float*)d_in[1];
    const float* w1     = (const float*)d_in[2];
    const float* w2     = (const float*)d_in[3];
    const float* bias   = (const float*)d_in[4];
    float* out = (float*)d_out;

    const int n = out_size;  // 500000 rows
    const int blocks = (n + WARPS_PER_BLOCK - 1) / WARPS_PER_BLOCK;
    gemv272_warp_kernel<<<blocks, THREADS>>>(inputs, kern, w1, w2, bias, out, n);
}